// round 4
// baseline (speedup 1.0000x reference)
#include <cuda_runtime.h>
#include <math.h>

#define BB 16
#define NN 8
#define TT 65536
#define CHUNKS 32
#define TPB 256
#define TPC (TT / CHUNKS)        // 2048 floats per chunk per row
#define K4 (TPC / (4 * TPB))     // 2 float4 iterations per thread

// Per-(chunk,batch) partial sums, no atomics: [CHUNKS*BB][64]
__device__ float g_part[CHUNKS * BB * NN * NN];

// Pairwise squared-difference partial sums.
// Grid (CHUNKS, BB), 256 thr, occ 4 -> whole grid is ONE resident wave.
// Two passes of a 4(i) x 8(j) register tile; y chunk re-read on pass 2 from L2.
__global__ __launch_bounds__(TPB, 4)
void sp_pair(const float* __restrict__ inp, const float* __restrict__ tgt) {
    const int b = blockIdx.y;
    const int chunk = blockIdx.x;

    const float4* __restrict__ X = reinterpret_cast<const float4*>(inp)
                                   + (size_t)b * NN * (TT / 4) + (size_t)chunk * (TPC / 4);
    const float4* __restrict__ Y = reinterpret_cast<const float4*>(tgt)
                                   + (size_t)b * NN * (TT / 4) + (size_t)chunk * (TPC / 4);

    __shared__ float sred[TPB / 32][4 * NN];
    float* const gout = &g_part[(chunk * BB + b) * NN * NN];
    const int warp = threadIdx.x >> 5;
    const int lane = threadIdx.x & 31;

#pragma unroll
    for (int pass = 0; pass < 2; pass++) {
        const int ibase = pass * 4;
        float acc[4][NN];
#pragma unroll
        for (int i = 0; i < 4; i++)
#pragma unroll
            for (int j = 0; j < NN; j++) acc[i][j] = 0.f;

#pragma unroll
        for (int k = 0; k < K4; k++) {
            const int t4 = threadIdx.x + k * TPB;
            float4 x[4];
#pragma unroll
            for (int i = 0; i < 4; i++)
                x[i] = __ldg(&X[(size_t)(ibase + i) * (TT / 4) + t4]);
#pragma unroll
            for (int j = 0; j < NN; j++) {
                const float4 y = __ldg(&Y[(size_t)j * (TT / 4) + t4]);
#pragma unroll
                for (int i = 0; i < 4; i++) {
                    const float d0 = x[i].x - y.x;
                    const float d1 = x[i].y - y.y;
                    const float d2 = x[i].z - y.z;
                    const float d3 = x[i].w - y.w;
                    acc[i][j] = fmaf(d0, d0, acc[i][j]);
                    acc[i][j] = fmaf(d1, d1, acc[i][j]);
                    acc[i][j] = fmaf(d2, d2, acc[i][j]);
                    acc[i][j] = fmaf(d3, d3, acc[i][j]);
                }
            }
        }

        // Warp tree-reduce the 32 accumulators.
#pragma unroll
        for (int i = 0; i < 4; i++)
#pragma unroll
            for (int j = 0; j < NN; j++) {
                float v = acc[i][j];
                v += __shfl_xor_sync(0xffffffffu, v, 16);
                v += __shfl_xor_sync(0xffffffffu, v, 8);
                v += __shfl_xor_sync(0xffffffffu, v, 4);
                v += __shfl_xor_sync(0xffffffffu, v, 2);
                v += __shfl_xor_sync(0xffffffffu, v, 1);
                acc[i][j] = v;
            }

        if (lane == 0) {
#pragma unroll
            for (int i = 0; i < 4; i++)
#pragma unroll
                for (int j = 0; j < NN; j++) sred[warp][i * NN + j] = acc[i][j];
        }
        __syncthreads();
        if (threadIdx.x < 4 * NN) {
            float s = 0.f;
#pragma unroll
            for (int w = 0; w < TPB / 32; w++) s += sred[w][threadIdx.x];
            gout[ibase * NN + threadIdx.x] = s;
        }
        __syncthreads();
    }
}

// Chunk-reduce + Sinkhorn-Knopp (10 iters) + loss + argmax.
// One block of 128 threads (register-heavy Sinkhorn lives on warp 0 only,
// but reg allocation is per-thread: 128 * ~160 regs fits; 1024 did not).
__global__ __launch_bounds__(128)
void sp_finish(float* __restrict__ out, int out_size) {
    __shared__ float s_pl[BB][NN * NN];
    __shared__ float s_loss;
    __shared__ int s_pat[BB][NN];

    // Chunk reduction: 1024 (b,ij) entries strided over 128 threads.
    for (int idx = threadIdx.x; idx < BB * NN * NN; idx += 128) {
        const int b = idx >> 6;
        const int ij = idx & 63;
        float s = 0.f;
#pragma unroll
        for (int c = 0; c < CHUNKS; c++)
            s += g_part[(c * BB + b) * NN * NN + ij];
        s_pl[b][ij] = s * (1.0f / (float)TT);
    }
    __syncthreads();

    // Warp 0, lanes 0..15: per-batch Sinkhorn entirely in registers.
    if (threadIdx.x < 32) {
        const int b = threadIdx.x;
        float loss_b = 0.f;
        float pl[NN][NN];
        float Z[NN][NN];

        if (b < BB) {
#pragma unroll
            for (int i = 0; i < NN; i++)
#pragma unroll
                for (int j = 0; j < NN; j++) {
                    const float v = s_pl[b][i * NN + j];
                    pl[i][j] = v;
                    Z[i][j] = -v;   // COLDNESS = 1
                }

#pragma unroll 1
            for (int it = 0; it < 10; it++) {
#pragma unroll
                for (int j = 0; j < NN; j++) {         // lse over axis=1 (i)
                    float m = Z[0][j];
#pragma unroll
                    for (int i = 1; i < NN; i++) m = fmaxf(m, Z[i][j]);
                    float s = 0.f;
#pragma unroll
                    for (int i = 0; i < NN; i++) s += expf(Z[i][j] - m);
                    const float l = m + logf(s);
#pragma unroll
                    for (int i = 0; i < NN; i++) Z[i][j] -= l;
                }
#pragma unroll
                for (int i = 0; i < NN; i++) {         // lse over axis=2 (j)
                    float m = Z[i][0];
#pragma unroll
                    for (int j = 1; j < NN; j++) m = fmaxf(m, Z[i][j]);
                    float s = 0.f;
#pragma unroll
                    for (int j = 0; j < NN; j++) s += expf(Z[i][j] - m);
                    const float l = m + logf(s);
#pragma unroll
                    for (int j = 0; j < NN; j++) Z[i][j] -= l;
                }
            }

#pragma unroll
            for (int i = 0; i < NN; i++) {
                float best = Z[i][0];
                int bj = 0;
#pragma unroll
                for (int j = 1; j < NN; j++)
                    if (Z[i][j] > best) { best = Z[i][j]; bj = j; }
                s_pat[b][i] = bj;
#pragma unroll
                for (int j = 0; j < NN; j++)
                    loss_b += (pl[i][j] + Z[i][j]) * expf(Z[i][j]);
            }
        }

        float s = loss_b;
#pragma unroll
        for (int o = 16; o; o >>= 1) s += __shfl_xor_sync(0xffffffffu, s, o);
        if (threadIdx.x == 0) s_loss = s * (1.0f / (float)BB);
    }
    __syncthreads();

    // Output: loss then pattern (fp32), defensively handle layouts.
    const int full = 1 + BB * NN;   // 129
    if (out_size >= full) {
        if (threadIdx.x == 0) out[0] = s_loss;
        if (threadIdx.x < BB * NN)
            out[1 + threadIdx.x] = (float)s_pat[threadIdx.x >> 3][threadIdx.x & 7];
        for (int idx = full + (int)threadIdx.x; idx < out_size; idx += 128)
            out[idx] = 0.f;
    } else if (out_size == BB * NN) {
        if (threadIdx.x < BB * NN)
            out[threadIdx.x] = (float)s_pat[threadIdx.x >> 3][threadIdx.x & 7];
    } else {
        if (threadIdx.x == 0 && out_size > 0) out[0] = s_loss;
        for (int idx = 1 + (int)threadIdx.x; idx < out_size; idx += 128)
            out[idx] = 0.f;
    }
}

extern "C" void kernel_launch(void* const* d_in, const int* in_sizes, int n_in,
                              void* d_out, int out_size) {
    const float* inp = (const float*)d_in[0];
    const float* tgt = (const float*)d_in[1];

    dim3 grid(CHUNKS, BB);
    sp_pair<<<grid, TPB>>>(inp, tgt);
    sp_finish<<<1, 128>>>((float*)d_out, out_size);
}

// round 5
// speedup vs baseline: 1.0899x; 1.0899x over previous
#include <cuda_runtime.h>
#include <math.h>

#define BB 16
#define NN 8
#define TT 65536
#define CHUNKS 32
#define TPB 256
#define TPC (TT / CHUNKS)        // 2048 floats per chunk per row
#define K4 (TPC / (4 * TPB))     // 2 float4 iterations per thread

// Per-(chunk,batch) partial sums, no atomics: [CHUNKS*BB][64]
__device__ float g_part[CHUNKS * BB * NN * NN];

// Pairwise squared-difference partial sums.
// Grid (CHUNKS, BB), 256 thr, occ 4 -> whole grid is ONE resident wave.
__global__ __launch_bounds__(TPB, 4)
void sp_pair(const float* __restrict__ inp, const float* __restrict__ tgt) {
    const int b = blockIdx.y;
    const int chunk = blockIdx.x;

    const float4* __restrict__ X = reinterpret_cast<const float4*>(inp)
                                   + (size_t)b * NN * (TT / 4) + (size_t)chunk * (TPC / 4);
    const float4* __restrict__ Y = reinterpret_cast<const float4*>(tgt)
                                   + (size_t)b * NN * (TT / 4) + (size_t)chunk * (TPC / 4);

    __shared__ float sred[TPB / 32][4 * NN];
    float* const gout = &g_part[(chunk * BB + b) * NN * NN];
    const int warp = threadIdx.x >> 5;
    const int lane = threadIdx.x & 31;

#pragma unroll
    for (int pass = 0; pass < 2; pass++) {
        const int ibase = pass * 4;
        float acc[4][NN];
#pragma unroll
        for (int i = 0; i < 4; i++)
#pragma unroll
            for (int j = 0; j < NN; j++) acc[i][j] = 0.f;

#pragma unroll
        for (int k = 0; k < K4; k++) {
            const int t4 = threadIdx.x + k * TPB;
            float4 x[4];
#pragma unroll
            for (int i = 0; i < 4; i++)
                x[i] = __ldg(&X[(size_t)(ibase + i) * (TT / 4) + t4]);
#pragma unroll
            for (int j = 0; j < NN; j++) {
                const float4 y = __ldg(&Y[(size_t)j * (TT / 4) + t4]);
#pragma unroll
                for (int i = 0; i < 4; i++) {
                    const float d0 = x[i].x - y.x;
                    const float d1 = x[i].y - y.y;
                    const float d2 = x[i].z - y.z;
                    const float d3 = x[i].w - y.w;
                    acc[i][j] = fmaf(d0, d0, acc[i][j]);
                    acc[i][j] = fmaf(d1, d1, acc[i][j]);
                    acc[i][j] = fmaf(d2, d2, acc[i][j]);
                    acc[i][j] = fmaf(d3, d3, acc[i][j]);
                }
            }
        }

#pragma unroll
        for (int i = 0; i < 4; i++)
#pragma unroll
            for (int j = 0; j < NN; j++) {
                float v = acc[i][j];
                v += __shfl_xor_sync(0xffffffffu, v, 16);
                v += __shfl_xor_sync(0xffffffffu, v, 8);
                v += __shfl_xor_sync(0xffffffffu, v, 4);
                v += __shfl_xor_sync(0xffffffffu, v, 2);
                v += __shfl_xor_sync(0xffffffffu, v, 1);
                acc[i][j] = v;
            }

        if (lane == 0) {
#pragma unroll
            for (int i = 0; i < 4; i++)
#pragma unroll
                for (int j = 0; j < NN; j++) sred[warp][i * NN + j] = acc[i][j];
        }
        __syncthreads();
        if (threadIdx.x < 4 * NN) {
            float s = 0.f;
#pragma unroll
            for (int w = 0; w < TPB / 32; w++) s += sred[w][threadIdx.x];
            gout[ibase * NN + threadIdx.x] = s;
        }
        __syncthreads();
    }
}

// Chunk-reduce + Sinkhorn + loss + argmax, parallelized 8x:
// 128 threads; thread (b, j) owns column j of batch b's 8x8 matrix.
// axis=1 lse: thread-local registers. axis=2 lse: shfl_xor over the 8-lane group.
__global__ __launch_bounds__(128)
void sp_finish(float* __restrict__ out, int out_size) {
    const int tid = threadIdx.x;
    const int b = tid >> 3;        // 0..15
    const int j = tid & 7;         // 0..7

    // Chunk reduction: thread (b,j) gathers pl[i][j] for i=0..7.
    // g_part index: (c*BB + b)*64 + i*8 + j -> 8-lane groups read consecutive floats.
    float pl[NN];
#pragma unroll
    for (int i = 0; i < NN; i++) pl[i] = 0.f;
#pragma unroll
    for (int c = 0; c < CHUNKS; c++) {
        const float* base = &g_part[(c * BB + b) * NN * NN + j];
#pragma unroll
        for (int i = 0; i < NN; i++) pl[i] += base[i * NN];
    }
    float z[NN];
#pragma unroll
    for (int i = 0; i < NN; i++) {
        pl[i] *= (1.0f / (float)TT);
        z[i] = -pl[i];             // COLDNESS = 1
    }

#pragma unroll 1
    for (int it = 0; it < 10; it++) {
        // axis=1 lse (over i) — local to this thread's column.
        {
            float m = z[0];
#pragma unroll
            for (int i = 1; i < NN; i++) m = fmaxf(m, z[i]);
            float s = 0.f;
#pragma unroll
            for (int i = 0; i < NN; i++) s += expf(z[i] - m);
            const float l = m + logf(s);
#pragma unroll
            for (int i = 0; i < NN; i++) z[i] -= l;
        }
        // axis=2 lse (over j) — butterfly across the 8-lane group, all rows pipelined.
        {
            float m[NN];
#pragma unroll
            for (int i = 0; i < NN; i++) m[i] = z[i];
#pragma unroll
            for (int off = 1; off < NN; off <<= 1)
#pragma unroll
                for (int i = 0; i < NN; i++)
                    m[i] = fmaxf(m[i], __shfl_xor_sync(0xffffffffu, m[i], off));
            float e[NN];
#pragma unroll
            for (int i = 0; i < NN; i++) e[i] = expf(z[i] - m[i]);
#pragma unroll
            for (int off = 1; off < NN; off <<= 1)
#pragma unroll
                for (int i = 0; i < NN; i++)
                    e[i] += __shfl_xor_sync(0xffffffffu, e[i], off);
#pragma unroll
            for (int i = 0; i < NN; i++) z[i] -= m[i] + logf(e[i]);
        }
    }

    // Per-thread loss contribution.
    float loss_t = 0.f;
#pragma unroll
    for (int i = 0; i < NN; i++)
        loss_t += (pl[i] + z[i]) * expf(z[i]);

    // argmax over j (across the 8-lane group) for each row i; ties -> lowest j.
    float av[NN];
    int aj[NN];
#pragma unroll
    for (int i = 0; i < NN; i++) { av[i] = z[i]; aj[i] = j; }
#pragma unroll
    for (int off = 1; off < NN; off <<= 1)
#pragma unroll
        for (int i = 0; i < NN; i++) {
            const float ov = __shfl_xor_sync(0xffffffffu, av[i], off);
            const int oj = __shfl_xor_sync(0xffffffffu, aj[i], off);
            if (ov > av[i] || (ov == av[i] && oj < aj[i])) { av[i] = ov; aj[i] = oj; }
        }

    // Loss reduce over 128 threads.
    __shared__ float s_wloss[4];
#pragma unroll
    for (int off = 16; off; off >>= 1)
        loss_t += __shfl_xor_sync(0xffffffffu, loss_t, off);
    if ((tid & 31) == 0) s_wloss[tid >> 5] = loss_t;
    __syncthreads();
    float loss = 0.f;
    if (tid == 0) {
#pragma unroll
        for (int w = 0; w < 4; w++) loss += s_wloss[w];
        loss *= (1.0f / (float)BB);
    }

    // Output: loss then pattern (fp32), defensively handle layouts.
    const int full = 1 + BB * NN;   // 129
    if (out_size >= full) {
        if (tid == 0) out[0] = loss;
        if (j == 0) {
#pragma unroll
            for (int i = 0; i < NN; i++) out[1 + b * NN + i] = (float)aj[i];
        }
        for (int idx = full + tid; idx < out_size; idx += 128) out[idx] = 0.f;
    } else if (out_size == BB * NN) {
        if (j == 0) {
#pragma unroll
            for (int i = 0; i < NN; i++) out[b * NN + i] = (float)aj[i];
        }
    } else {
        if (tid == 0 && out_size > 0) out[0] = loss;
        for (int idx = 1 + tid; idx < out_size; idx += 128) out[idx] = 0.f;
    }
}

extern "C" void kernel_launch(void* const* d_in, const int* in_sizes, int n_in,
                              void* d_out, int out_size) {
    const float* inp = (const float*)d_in[0];
    const float* tgt = (const float*)d_in[1];

    dim3 grid(CHUNKS, BB);
    sp_pair<<<grid, TPB>>>(inp, tgt);
    sp_finish<<<1, 128>>>((float*)d_out, out_size);
}

// round 6
// speedup vs baseline: 1.3288x; 1.2192x over previous
#include <cuda_runtime.h>
#include <math.h>

#define BB 16
#define NN 8
#define TT 65536
#define CHUNKS 32
#define TPB 256
#define TPC (TT / CHUNKS)        // 2048 floats per chunk per row
#define K4 (TPC / (4 * TPB))     // 2 float4 iterations per thread

// Per-(chunk,batch) partial sums, no atomics: [CHUNKS*BB][64]
__device__ float g_part[CHUNKS * BB * NN * NN];

// Pairwise squared-difference partial sums.
// Grid (CHUNKS, BB), 256 thr, occ 4 -> whole grid is ONE resident wave.
__global__ __launch_bounds__(TPB, 4)
void sp_pair(const float* __restrict__ inp, const float* __restrict__ tgt) {
    const int b = blockIdx.y;
    const int chunk = blockIdx.x;

    const float4* __restrict__ X = reinterpret_cast<const float4*>(inp)
                                   + (size_t)b * NN * (TT / 4) + (size_t)chunk * (TPC / 4);
    const float4* __restrict__ Y = reinterpret_cast<const float4*>(tgt)
                                   + (size_t)b * NN * (TT / 4) + (size_t)chunk * (TPC / 4);

    __shared__ float sred[TPB / 32][4 * NN];
    float* const gout = &g_part[(chunk * BB + b) * NN * NN];
    const int warp = threadIdx.x >> 5;
    const int lane = threadIdx.x & 31;

#pragma unroll
    for (int pass = 0; pass < 2; pass++) {
        const int ibase = pass * 4;
        float acc[4][NN];
#pragma unroll
        for (int i = 0; i < 4; i++)
#pragma unroll
            for (int j = 0; j < NN; j++) acc[i][j] = 0.f;

#pragma unroll
        for (int k = 0; k < K4; k++) {
            const int t4 = threadIdx.x + k * TPB;
            float4 x[4];
#pragma unroll
            for (int i = 0; i < 4; i++)
                x[i] = __ldg(&X[(size_t)(ibase + i) * (TT / 4) + t4]);
#pragma unroll
            for (int j = 0; j < NN; j++) {
                const float4 y = __ldg(&Y[(size_t)j * (TT / 4) + t4]);
#pragma unroll
                for (int i = 0; i < 4; i++) {
                    const float d0 = x[i].x - y.x;
                    const float d1 = x[i].y - y.y;
                    const float d2 = x[i].z - y.z;
                    const float d3 = x[i].w - y.w;
                    acc[i][j] = fmaf(d0, d0, acc[i][j]);
                    acc[i][j] = fmaf(d1, d1, acc[i][j]);
                    acc[i][j] = fmaf(d2, d2, acc[i][j]);
                    acc[i][j] = fmaf(d3, d3, acc[i][j]);
                }
            }
        }

#pragma unroll
        for (int i = 0; i < 4; i++)
#pragma unroll
            for (int j = 0; j < NN; j++) {
                float v = acc[i][j];
                v += __shfl_xor_sync(0xffffffffu, v, 16);
                v += __shfl_xor_sync(0xffffffffu, v, 8);
                v += __shfl_xor_sync(0xffffffffu, v, 4);
                v += __shfl_xor_sync(0xffffffffu, v, 2);
                v += __shfl_xor_sync(0xffffffffu, v, 1);
                acc[i][j] = v;
            }

        if (lane == 0) {
#pragma unroll
            for (int i = 0; i < 4; i++)
#pragma unroll
                for (int j = 0; j < NN; j++) sred[warp][i * NN + j] = acc[i][j];
        }
        __syncthreads();
        if (threadIdx.x < 4 * NN) {
            float s = 0.f;
#pragma unroll
            for (int w = 0; w < TPB / 32; w++) s += sred[w][threadIdx.x];
            gout[ibase * NN + threadIdx.x] = s;
        }
        __syncthreads();
    }
}

// Chunk-reduce + Sinkhorn + loss + argmax, parallelized 8x.
// 128 threads; thread (b, j) owns column j of batch b's 8x8 matrix.
// Fast-math __expf/__logf; no max-shift (values bounded in [-~30, 0] -> safe).
__global__ __launch_bounds__(128)
void sp_finish(float* __restrict__ out, int out_size) {
    const int tid = threadIdx.x;
    const int b = tid >> 3;        // 0..15
    const int j = tid & 7;         // 0..7

    // Chunk reduction: thread (b,j) gathers pl[i][j] for i=0..7.
    float pl[NN];
#pragma unroll
    for (int i = 0; i < NN; i++) pl[i] = 0.f;
#pragma unroll
    for (int c = 0; c < CHUNKS; c++) {
        const float* base = &g_part[(c * BB + b) * NN * NN + j];
#pragma unroll
        for (int i = 0; i < NN; i++) pl[i] += __ldg(&base[i * NN]);
    }
    float z[NN];
#pragma unroll
    for (int i = 0; i < NN; i++) {
        pl[i] *= (1.0f / (float)TT);
        z[i] = -pl[i];             // COLDNESS = 1
    }

#pragma unroll 1
    for (int it = 0; it < 10; it++) {
        // axis=1 lse (over i): thread-local. No max-shift needed (bounded).
        {
            float s = 0.f;
#pragma unroll
            for (int i = 0; i < NN; i++) s += __expf(z[i]);
            const float l = __logf(s);
#pragma unroll
            for (int i = 0; i < NN; i++) z[i] -= l;
        }
        // axis=2 lse (over j): butterfly sum-of-exp across the 8-lane group.
        {
            float e[NN];
#pragma unroll
            for (int i = 0; i < NN; i++) e[i] = __expf(z[i]);
#pragma unroll
            for (int off = 1; off < NN; off <<= 1)
#pragma unroll
                for (int i = 0; i < NN; i++)
                    e[i] += __shfl_xor_sync(0xffffffffu, e[i], off);
#pragma unroll
            for (int i = 0; i < NN; i++) z[i] -= __logf(e[i]);
        }
    }

    // Per-thread loss contribution.
    float loss_t = 0.f;
#pragma unroll
    for (int i = 0; i < NN; i++)
        loss_t += (pl[i] + z[i]) * __expf(z[i]);

    // argmax over j (across the 8-lane group) for each row i; ties -> lowest j.
    float av[NN];
    int aj[NN];
#pragma unroll
    for (int i = 0; i < NN; i++) { av[i] = z[i]; aj[i] = j; }
#pragma unroll
    for (int off = 1; off < NN; off <<= 1)
#pragma unroll
        for (int i = 0; i < NN; i++) {
            const float ov = __shfl_xor_sync(0xffffffffu, av[i], off);
            const int oj = __shfl_xor_sync(0xffffffffu, aj[i], off);
            if (ov > av[i] || (ov == av[i] && oj < aj[i])) { av[i] = ov; aj[i] = oj; }
        }

    // Loss reduce over 128 threads.
    __shared__ float s_wloss[4];
#pragma unroll
    for (int off = 16; off; off >>= 1)
        loss_t += __shfl_xor_sync(0xffffffffu, loss_t, off);
    if ((tid & 31) == 0) s_wloss[tid >> 5] = loss_t;
    __syncthreads();
    float loss = 0.f;
    if (tid == 0) {
#pragma unroll
        for (int w = 0; w < 4; w++) loss += s_wloss[w];
        loss *= (1.0f / (float)BB);
    }

    // Output: loss then pattern (fp32), defensively handle layouts.
    const int full = 1 + BB * NN;   // 129
    if (out_size >= full) {
        if (tid == 0) out[0] = loss;
        if (j == 0) {
#pragma unroll
            for (int i = 0; i < NN; i++) out[1 + b * NN + i] = (float)aj[i];
        }
        for (int idx = full + tid; idx < out_size; idx += 128) out[idx] = 0.f;
    } else if (out_size == BB * NN) {
        if (j == 0) {
#pragma unroll
            for (int i = 0; i < NN; i++) out[b * NN + i] = (float)aj[i];
        }
    } else {
        if (tid == 0 && out_size > 0) out[0] = loss;
        for (int idx = 1 + tid; idx < out_size; idx += 128) out[idx] = 0.f;
    }
}

extern "C" void kernel_launch(void* const* d_in, const int* in_sizes, int n_in,
                              void* d_out, int out_size) {
    const float* inp = (const float*)d_in[0];
    const float* tgt = (const float*)d_in[1];

    dim3 grid(CHUNKS, BB);
    sp_pair<<<grid, TPB>>>(inp, tgt);
    sp_finish<<<1, 128>>>((float*)d_out, out_size);
}

// round 8
// speedup vs baseline: 1.4600x; 1.0988x over previous
#include <cuda_runtime.h>
#include <math.h>

#define BB 16
#define NN 8
#define TT 65536
#define CHUNKS 32
#define TPB 256
#define TPC (TT / CHUNKS)        // 2048 floats per chunk per row
#define K4 (TPC / (4 * TPB))     // 2 float4 iterations per thread
#define NCELL (NN * NN)          // 64

// Scratch: [BB][64 cells][CHUNKS] -> cross-chunk sum is contiguous (float4-able).
__device__ float g_part[BB * NCELL * CHUNKS];
__device__ unsigned int g_ctr;   // zero-initialized; last block resets to 0

__global__ __launch_bounds__(TPB, 4)
void sp_fused(const float* __restrict__ inp, const float* __restrict__ tgt,
              float* __restrict__ out, int out_size) {
    const int b = blockIdx.y;
    const int chunk = blockIdx.x;
    const int tid = threadIdx.x;

    const float4* __restrict__ X = reinterpret_cast<const float4*>(inp)
                                   + (size_t)b * NN * (TT / 4) + (size_t)chunk * (TPC / 4);
    const float4* __restrict__ Y = reinterpret_cast<const float4*>(tgt)
                                   + (size_t)b * NN * (TT / 4) + (size_t)chunk * (TPC / 4);

    __shared__ float sred[TPB / 32][4 * NN];
    const int warp = tid >> 5;
    const int lane = tid & 31;

    // ---- Phase 1: pairwise squared-diff partials (2-pass 4x8 register tile) ----
#pragma unroll
    for (int pass = 0; pass < 2; pass++) {
        const int ibase = pass * 4;
        float acc[4][NN];
#pragma unroll
        for (int i = 0; i < 4; i++)
#pragma unroll
            for (int j = 0; j < NN; j++) acc[i][j] = 0.f;

#pragma unroll
        for (int k = 0; k < K4; k++) {
            const int t4 = tid + k * TPB;
            float4 x[4];
#pragma unroll
            for (int i = 0; i < 4; i++)
                x[i] = __ldg(&X[(size_t)(ibase + i) * (TT / 4) + t4]);
#pragma unroll
            for (int j = 0; j < NN; j++) {
                const float4 y = __ldg(&Y[(size_t)j * (TT / 4) + t4]);
#pragma unroll
                for (int i = 0; i < 4; i++) {
                    const float d0 = x[i].x - y.x;
                    const float d1 = x[i].y - y.y;
                    const float d2 = x[i].z - y.z;
                    const float d3 = x[i].w - y.w;
                    acc[i][j] = fmaf(d0, d0, acc[i][j]);
                    acc[i][j] = fmaf(d1, d1, acc[i][j]);
                    acc[i][j] = fmaf(d2, d2, acc[i][j]);
                    acc[i][j] = fmaf(d3, d3, acc[i][j]);
                }
            }
        }

#pragma unroll
        for (int i = 0; i < 4; i++)
#pragma unroll
            for (int j = 0; j < NN; j++) {
                float v = acc[i][j];
                v += __shfl_xor_sync(0xffffffffu, v, 16);
                v += __shfl_xor_sync(0xffffffffu, v, 8);
                v += __shfl_xor_sync(0xffffffffu, v, 4);
                v += __shfl_xor_sync(0xffffffffu, v, 2);
                v += __shfl_xor_sync(0xffffffffu, v, 1);
                acc[i][j] = v;
            }

        if (lane == 0) {
#pragma unroll
            for (int i = 0; i < 4; i++)
#pragma unroll
                for (int j = 0; j < NN; j++) sred[warp][i * NN + j] = acc[i][j];
        }
        __syncthreads();
        if (tid < 4 * NN) {
            float s = 0.f;
#pragma unroll
            for (int w = 0; w < TPB / 32; w++) s += sred[w][tid];
            const int cell = ibase * NN + tid;   // global i*NN+j
            g_part[(b * NCELL + cell) * CHUNKS + chunk] = s;
        }
        __syncthreads();
    }

    // ---- Arrival counter: last of 512 blocks finishes the job ----
    __shared__ unsigned int s_last;
    if (tid == 0) {
        __threadfence();
        s_last = (atomicAdd(&g_ctr, 1u) == (unsigned)(CHUNKS * BB - 1)) ? 1u : 0u;
    }
    __syncthreads();
    if (!s_last) return;
    if (tid == 0) g_ctr = 0;       // reset for next graph replay

    // ---- Phase 2 (last block only): chunk reduction, L1-bypass loads ----
    __shared__ float s_pl[BB * NCELL];
    for (int cell = tid; cell < BB * NCELL; cell += TPB) {
        const float4* p = reinterpret_cast<const float4*>(&g_part[cell * CHUNKS]);
        float4 a = __ldcv(p + 0);
        float s = a.x + a.y + a.z + a.w;
#pragma unroll
        for (int q = 1; q < CHUNKS / 4; q++) {
            const float4 v = __ldcv(p + q);
            s += v.x + v.y + v.z + v.w;
        }
        s_pl[cell] = s * (1.0f / (float)TT);
    }
    __syncthreads();

    // ---- Phase 3: Sinkhorn (threads 0..127; thread = (batch, column j)) ----
    float loss_t = 0.f;
    int aj[NN];
    const int sb = tid >> 3;       // batch
    const int sj = tid & 7;        // column

    if (tid < 128) {
        float pl[NN], z[NN];
#pragma unroll
        for (int i = 0; i < NN; i++) {
            pl[i] = s_pl[sb * NCELL + i * NN + sj];
            z[i] = -pl[i];         // COLDNESS = 1
        }

#pragma unroll 1
        for (int it = 0; it < 10; it++) {
            // axis=1 lse (over i): thread-local; values bounded, no max-shift.
            float s = 0.f;
#pragma unroll
            for (int i = 0; i < NN; i++) s += __expf(z[i]);
            const float l = __logf(s);
#pragma unroll
            for (int i = 0; i < NN; i++) z[i] -= l;
            // axis=2 lse (over j): butterfly over the 8-lane group.
            float e[NN];
#pragma unroll
            for (int i = 0; i < NN; i++) e[i] = __expf(z[i]);
#pragma unroll
            for (int off = 1; off < NN; off <<= 1)
#pragma unroll
                for (int i = 0; i < NN; i++)
                    e[i] += __shfl_xor_sync(0xffffffffu, e[i], off);
#pragma unroll
            for (int i = 0; i < NN; i++) z[i] -= __logf(e[i]);
        }

#pragma unroll
        for (int i = 0; i < NN; i++)
            loss_t += (pl[i] + z[i]) * __expf(z[i]);

        // argmax over j per row i; ties -> lowest j.
        float av[NN];
#pragma unroll
        for (int i = 0; i < NN; i++) { av[i] = z[i]; aj[i] = sj; }
#pragma unroll
        for (int off = 1; off < NN; off <<= 1)
#pragma unroll
            for (int i = 0; i < NN; i++) {
                const float ov = __shfl_xor_sync(0xffffffffu, av[i], off);
                const int oj = __shfl_xor_sync(0xffffffffu, aj[i], off);
                if (ov > av[i] || (ov == av[i] && oj < aj[i])) { av[i] = ov; aj[i] = oj; }
            }
    }

    // Loss reduce (warps 0-3 carry nonzero; others contribute 0).
    __shared__ float s_wloss[TPB / 32];
#pragma unroll
    for (int off = 16; off; off >>= 1)
        loss_t += __shfl_xor_sync(0xffffffffu, loss_t, off);
    if (lane == 0) s_wloss[warp] = loss_t;
    __syncthreads();
    float loss = 0.f;
    if (tid == 0) {
#pragma unroll
        for (int w = 0; w < 4; w++) loss += s_wloss[w];
        loss *= (1.0f / (float)BB);
    }

    // ---- Output: loss then pattern (fp32); defensive layouts ----
    const int full = 1 + BB * NN;   // 129
    if (out_size >= full) {
        if (tid == 0) out[0] = loss;
        if (tid < 128 && sj == 0) {
#pragma unroll
            for (int i = 0; i < NN; i++) out[1 + sb * NN + i] = (float)aj[i];
        }
        for (int idx = full + tid; idx < out_size; idx += TPB) out[idx] = 0.f;
    } else if (out_size == BB * NN) {
        if (tid < 128 && sj == 0) {
#pragma unroll
            for (int i = 0; i < NN; i++) out[sb * NN + i] = (float)aj[i];
        }
    } else {
        if (tid == 0 && out_size > 0) out[0] = loss;
        for (int idx = 1 + tid; idx < out_size; idx += TPB) out[idx] = 0.f;
    }
}

extern "C" void kernel_launch(void* const* d_in, const int* in_sizes, int n_in,
                              void* d_out, int out_size) {
    const float* inp = (const float*)d_in[0];
    const float* tgt = (const float*)d_in[1];

    dim3 grid(CHUNKS, BB);
    sp_fused<<<grid, TPB>>>(inp, tgt, (float*)d_out, out_size);
}

// round 9
// speedup vs baseline: 2.1586x; 1.4784x over previous
#include <cuda_runtime.h>
#include <math.h>

#define BB 16
#define NN 8
#define TT 65536
#define CHUNKS 32
#define TPB 256
#define TPC (TT / CHUNKS)        // 2048 floats per chunk per row
#define SUB 8                    // substeps per chunk
#define SCOLS 64                 // float4 columns per substep (256 floats)
#define NCELL (NN * NN)          // 64

// Scratch: [BB][64 cells][CHUNKS] -> cross-chunk sum is contiguous (float4-able).
__device__ float g_part[BB * NCELL * CHUNKS];
__device__ unsigned int g_ctr;   // zero-initialized; last block resets to 0

__global__ __launch_bounds__(TPB, 4)
void sp_fused(const float* __restrict__ inp, const float* __restrict__ tgt,
              float* __restrict__ out, int out_size) {
    const int b = blockIdx.y;
    const int chunk = blockIdx.x;
    const int tid = threadIdx.x;
    const int col = tid & 63;      // float4 column within substep
    const int g = tid >> 6;        // i-group: rows {2g, 2g+1}
    const int warp = tid >> 5;
    const int lane = tid & 31;

    const float4* __restrict__ X = reinterpret_cast<const float4*>(inp)
                                   + (size_t)b * NN * (TT / 4) + (size_t)chunk * (TPC / 4);
    const float4* __restrict__ Y = reinterpret_cast<const float4*>(tgt)
                                   + (size_t)b * NN * (TT / 4) + (size_t)chunk * (TPC / 4);

    __shared__ float4 ybuf[2][NN][SCOLS];   // 16 KB double-buffered Y stage
    __shared__ float sred[TPB / 32][16];

    // ---- Phase 1: single-pass 2x8 tile, Y staged via smem, pipelined ----
    float acc[2][NN];
#pragma unroll
    for (int i = 0; i < 2; i++)
#pragma unroll
        for (int j = 0; j < NN; j++) acc[i][j] = 0.f;

    // Cooperative Y mapping: thread loads rows g and g+4 at its col.
    float4 yreg0 = __ldg(&Y[(size_t)g * (TT / 4) + col]);
    float4 yreg1 = __ldg(&Y[(size_t)(g + 4) * (TT / 4) + col]);
    float4 xreg0 = __ldg(&X[(size_t)(2 * g) * (TT / 4) + col]);
    float4 xreg1 = __ldg(&X[(size_t)(2 * g + 1) * (TT / 4) + col]);
    ybuf[0][g][col] = yreg0;
    ybuf[0][g + 4][col] = yreg1;
    __syncthreads();

#pragma unroll
    for (int s = 0; s < SUB; s++) {
        const int p = s & 1;
        const float4 xc0 = xreg0;
        const float4 xc1 = xreg1;
        if (s < SUB - 1) {
            const int t4 = (s + 1) * SCOLS + col;
            yreg0 = __ldg(&Y[(size_t)g * (TT / 4) + t4]);
            yreg1 = __ldg(&Y[(size_t)(g + 4) * (TT / 4) + t4]);
            xreg0 = __ldg(&X[(size_t)(2 * g) * (TT / 4) + t4]);
            xreg1 = __ldg(&X[(size_t)(2 * g + 1) * (TT / 4) + t4]);
        }
#pragma unroll
        for (int j = 0; j < NN; j++) {
            const float4 y = ybuf[p][j][col];
            float d;
            d = xc0.x - y.x; acc[0][j] = fmaf(d, d, acc[0][j]);
            d = xc0.y - y.y; acc[0][j] = fmaf(d, d, acc[0][j]);
            d = xc0.z - y.z; acc[0][j] = fmaf(d, d, acc[0][j]);
            d = xc0.w - y.w; acc[0][j] = fmaf(d, d, acc[0][j]);
            d = xc1.x - y.x; acc[1][j] = fmaf(d, d, acc[1][j]);
            d = xc1.y - y.y; acc[1][j] = fmaf(d, d, acc[1][j]);
            d = xc1.z - y.z; acc[1][j] = fmaf(d, d, acc[1][j]);
            d = xc1.w - y.w; acc[1][j] = fmaf(d, d, acc[1][j]);
        }
        if (s < SUB - 1) {
            ybuf[1 - p][g][col] = yreg0;
            ybuf[1 - p][g + 4][col] = yreg1;
            __syncthreads();
        }
    }

    // Warp reduce the 16 accumulators (cols within warp).
#pragma unroll
    for (int i = 0; i < 2; i++)
#pragma unroll
        for (int j = 0; j < NN; j++) {
            float v = acc[i][j];
            v += __shfl_xor_sync(0xffffffffu, v, 16);
            v += __shfl_xor_sync(0xffffffffu, v, 8);
            v += __shfl_xor_sync(0xffffffffu, v, 4);
            v += __shfl_xor_sync(0xffffffffu, v, 2);
            v += __shfl_xor_sync(0xffffffffu, v, 1);
            acc[i][j] = v;
        }
    if (lane == 0) {
#pragma unroll
        for (int i = 0; i < 2; i++)
#pragma unroll
            for (int j = 0; j < NN; j++) sred[warp][i * NN + j] = acc[i][j];
    }
    __syncthreads();
    // Cell (i,j) lives in i-group g=i>>1 = warps {2g, 2g+1}.
    if (tid < NCELL) {
        const int ci = tid >> 3, cj = tid & 7;
        const int cg = ci >> 1, cii = ci & 1;
        const float s = sred[2 * cg][cii * NN + cj] + sred[2 * cg + 1][cii * NN + cj];
        g_part[(b * NCELL + tid) * CHUNKS + chunk] = s;
    }

    // ---- Arrival counter: last of 512 blocks finishes the job ----
    __shared__ unsigned int s_last;
    if (tid == 0) {
        __threadfence();
        s_last = (atomicAdd(&g_ctr, 1u) == (unsigned)(CHUNKS * BB - 1)) ? 1u : 0u;
    }
    __syncthreads();
    if (!s_last) return;
    if (tid == 0) g_ctr = 0;       // reset for next graph replay

    // ---- Phase 2 (last block only): chunk reduction, L1-bypass loads ----
    __shared__ float s_pl[BB * NCELL];
    for (int cell = tid; cell < BB * NCELL; cell += TPB) {
        const float4* p = reinterpret_cast<const float4*>(&g_part[cell * CHUNKS]);
        float4 a = __ldcv(p + 0);
        float s = a.x + a.y + a.z + a.w;
#pragma unroll
        for (int q = 1; q < CHUNKS / 4; q++) {
            const float4 v = __ldcv(p + q);
            s += v.x + v.y + v.z + v.w;
        }
        s_pl[cell] = s * (1.0f / (float)TT);
    }
    __syncthreads();

    // ---- Phase 3: Sinkhorn (threads 0..127; thread = (batch, column j)) ----
    float loss_t = 0.f;
    int aj[NN];
    const int sb = tid >> 3;
    const int sj = tid & 7;

    if (tid < 128) {
        float pl[NN], z[NN];
#pragma unroll
        for (int i = 0; i < NN; i++) {
            pl[i] = s_pl[sb * NCELL + i * NN + sj];
            z[i] = -pl[i];         // COLDNESS = 1
        }

#pragma unroll 1
        for (int it = 0; it < 10; it++) {
            float s = 0.f;
#pragma unroll
            for (int i = 0; i < NN; i++) s += __expf(z[i]);
            const float l = __logf(s);
#pragma unroll
            for (int i = 0; i < NN; i++) z[i] -= l;
            float e[NN];
#pragma unroll
            for (int i = 0; i < NN; i++) e[i] = __expf(z[i]);
#pragma unroll
            for (int off = 1; off < NN; off <<= 1)
#pragma unroll
                for (int i = 0; i < NN; i++)
                    e[i] += __shfl_xor_sync(0xffffffffu, e[i], off);
#pragma unroll
            for (int i = 0; i < NN; i++) z[i] -= __logf(e[i]);
        }

#pragma unroll
        for (int i = 0; i < NN; i++)
            loss_t += (pl[i] + z[i]) * __expf(z[i]);

        float av[NN];
#pragma unroll
        for (int i = 0; i < NN; i++) { av[i] = z[i]; aj[i] = sj; }
#pragma unroll
        for (int off = 1; off < NN; off <<= 1)
#pragma unroll
            for (int i = 0; i < NN; i++) {
                const float ov = __shfl_xor_sync(0xffffffffu, av[i], off);
                const int oj = __shfl_xor_sync(0xffffffffu, aj[i], off);
                if (ov > av[i] || (ov == av[i] && oj < aj[i])) { av[i] = ov; aj[i] = oj; }
            }
    }

    __shared__ float s_wloss[TPB / 32];
#pragma unroll
    for (int off = 16; off; off >>= 1)
        loss_t += __shfl_xor_sync(0xffffffffu, loss_t, off);
    if (lane == 0) s_wloss[warp] = loss_t;
    __syncthreads();
    float loss = 0.f;
    if (tid == 0) {
#pragma unroll
        for (int w = 0; w < 4; w++) loss += s_wloss[w];
        loss *= (1.0f / (float)BB);
    }

    // ---- Output: loss then pattern (fp32); defensive layouts ----
    const int full = 1 + BB * NN;   // 129
    if (out_size >= full) {
        if (tid == 0) out[0] = loss;
        if (tid < 128 && sj == 0) {
#pragma unroll
            for (int i = 0; i < NN; i++) out[1 + sb * NN + i] = (float)aj[i];
        }
        for (int idx = full + tid; idx < out_size; idx += TPB) out[idx] = 0.f;
    } else if (out_size == BB * NN) {
        if (tid < 128 && sj == 0) {
#pragma unroll
            for (int i = 0; i < NN; i++) out[sb * NN + i] = (float)aj[i];
        }
    } else {
        if (tid == 0 && out_size > 0) out[0] = loss;
        for (int idx = 1 + tid; idx < out_size; idx += TPB) out[idx] = 0.f;
    }
}

extern "C" void kernel_launch(void* const* d_in, const int* in_sizes, int n_in,
                              void* d_out, int out_size) {
    const float* inp = (const float*)d_in[0];
    const float* tgt = (const float*)d_in[1];

    dim3 grid(CHUNKS, BB);
    sp_fused<<<grid, TPB>>>(inp, tgt, (float*)d_out, out_size);
}